// round 8
// baseline (speedup 1.0000x reference)
#include <cuda_runtime.h>
#include <cuda_bf16.h>
#include <cstdint>

// Problem constants: B=16, V=4096, E=768
#define BB 16
#define VV 4096
#define EE 768

// out[b,v,e] = seq[b,v,0]*flux_w[v,e] + flux_b[v,e]
//            + seq[b,v,2]*time_w[v,e] + time_b[v,e]
//            + (e even ? sin : cos)( seq[b,v,1] * exp(-e_even*ln(10000)/E) )
//
// R7: L2::evict_last weight loads, fixed to the legal 256-bit encoding
// (ld.global.nc.L2::evict_last.v4.b64). Thread now owns 8 consecutive e
// (one 32B load per weight table), block = 96 threads per v-row.
// Goal: keep the 50 MB weight tables L2-resident across graph replays
// while the 201 MB output stream self-evicts.

__device__ __forceinline__ void ldg_el_8f(const float* p, float4& a, float4& b) {
    uint64_t x0, x1, x2, x3;
    asm("ld.global.nc.L2::evict_last.v4.b64 {%0,%1,%2,%3}, [%4];"
        : "=l"(x0), "=l"(x1), "=l"(x2), "=l"(x3)
        : "l"(p));
    a.x = __uint_as_float((uint32_t)x0);  a.y = __uint_as_float((uint32_t)(x0 >> 32));
    a.z = __uint_as_float((uint32_t)x1);  a.w = __uint_as_float((uint32_t)(x1 >> 32));
    b.x = __uint_as_float((uint32_t)x2);  b.y = __uint_as_float((uint32_t)(x2 >> 32));
    b.z = __uint_as_float((uint32_t)x3);  b.w = __uint_as_float((uint32_t)(x3 >> 32));
}

__global__ __launch_bounds__(96) void bert_embed_kernel(
    const float* __restrict__ seq,   // [B, V, 3]
    const float* __restrict__ fw,    // [V, E]
    const float* __restrict__ fb,    // [V, E]
    const float* __restrict__ tw,    // [V, E]
    const float* __restrict__ tb,    // [V, E]
    float* __restrict__ out)         // [B, V, E]
{
    __shared__ float s_seq[BB * 3];  // 48 floats

    const int v = blockIdx.x;
    const int t = threadIdx.x;
    const int e = t * 8;                       // thread owns e..e+7 (32B aligned)
    const size_t base = (size_t)v * EE + e;

    // Stage seq for this v: thread t<48 loads (b = t/3, ch = t%3).
    if (t < BB * 3) {
        const int b = t / 3, ch = t % 3;
        s_seq[t] = __ldg(seq + ((size_t)b * VV + v) * 3 + ch);
    }

    // Weight reads as 256-bit L2::evict_last loads -> resident across replays.
    float4 wf0, wf1, bf0, bf1, wt0, wt1, bt0, bt1;
    ldg_el_8f(fw + base, wf0, wf1);
    ldg_el_8f(fb + base, bf0, bf1);
    ldg_el_8f(tw + base, wt0, wt1);
    ldg_el_8f(tb + base, bt0, bt1);

    // Combined bias: out = s0*wf + s2*wt + (bf+bt) + pe
    const float4 bs0 = make_float4(bf0.x + bt0.x, bf0.y + bt0.y,
                                   bf0.z + bt0.z, bf0.w + bt0.w);
    const float4 bs1 = make_float4(bf1.x + bt1.x, bf1.y + bt1.y,
                                   bf1.z + bt1.z, bf1.w + bt1.w);

    // div_term for the four sin/cos pairs this thread owns:
    // div_term[i] = exp(2i * (-ln(10000)/E)); 2i = e, e+2, e+4, e+6.
    const float c  = -9.210340371976184f / (float)EE;   // -ln(10000)/E
    const float d0 = __expf((float)(e + 0) * c);
    const float d1 = __expf((float)(e + 2) * c);
    const float d2 = __expf((float)(e + 4) * c);
    const float d3 = __expf((float)(e + 6) * c);

    __syncthreads();

    #pragma unroll
    for (int b = 0; b < BB; b++) {
        const float s0 = s_seq[b * 3 + 0];   // flux (LDS broadcast)
        const float s1 = s_seq[b * 3 + 1];   // passend
        const float s2 = s_seq[b * 3 + 2];   // time

        float sn0, cs0, sn1, cs1, sn2, cs2, sn3, cs3;
        __sincosf(s1 * d0, &sn0, &cs0);
        __sincosf(s1 * d1, &sn1, &cs1);
        __sincosf(s1 * d2, &sn2, &cs2);
        __sincosf(s1 * d3, &sn3, &cs3);

        float4 o0, o1;
        o0.x = fmaf(s0, wf0.x, fmaf(s2, wt0.x, bs0.x)) + sn0;
        o0.y = fmaf(s0, wf0.y, fmaf(s2, wt0.y, bs0.y)) + cs0;
        o0.z = fmaf(s0, wf0.z, fmaf(s2, wt0.z, bs0.z)) + sn1;
        o0.w = fmaf(s0, wf0.w, fmaf(s2, wt0.w, bs0.w)) + cs1;
        o1.x = fmaf(s0, wf1.x, fmaf(s2, wt1.x, bs1.x)) + sn2;
        o1.y = fmaf(s0, wf1.y, fmaf(s2, wt1.y, bs1.y)) + cs2;
        o1.z = fmaf(s0, wf1.z, fmaf(s2, wt1.z, bs1.z)) + sn3;
        o1.w = fmaf(s0, wf1.w, fmaf(s2, wt1.w, bs1.w)) + cs3;

        // Plain cached stores (2x STG.128) — best-measured write path.
        float4* po = reinterpret_cast<float4*>(out + (size_t)b * (VV * EE) + base);
        po[0] = o0;
        po[1] = o1;
    }
}

extern "C" void kernel_launch(void* const* d_in, const int* in_sizes, int n_in,
                              void* d_out, int out_size)
{
    const float* seq = (const float*)d_in[0];  // sequence [B,V,3]
    const float* fw  = (const float*)d_in[1];  // flux_w   [V,E]
    const float* fb  = (const float*)d_in[2];  // flux_b   [V,E]
    const float* tw  = (const float*)d_in[3];  // time_w   [V,E]
    const float* tb  = (const float*)d_in[4];  // time_b   [V,E]
    float* out = (float*)d_out;                // [B,V,E]

    dim3 grid(VV);
    dim3 block(EE / 8);  // 96 threads
    bert_embed_kernel<<<grid, block>>>(seq, fw, fb, tw, tb, out);
}

// round 9
// speedup vs baseline: 1.2493x; 1.2493x over previous
#include <cuda_runtime.h>
#include <cuda_bf16.h>

// Problem constants: B=16, V=4096, E=768
#define BB 16
#define VV 4096
#define EE 768

// out[b,v,e] = seq[b,v,0]*flux_w[v,e] + flux_b[v,e]
//            + seq[b,v,2]*time_w[v,e] + time_b[v,e]
//            + (e even ? sin : cos)( seq[b,v,1] * exp(-e_even*ln(10000)/E) )
//
// R8 = R5 structure (best: 43.1us, DRAM 65%) with ONE change:
// __launch_bounds__(192, 8) forces regs <= 40 -> 8 blocks/SM, 48 warps (75%
// theoretical occupancy, up from 36/56%). The kernel is DRAM-bound with all
// compute pipes at <20%, so more resident warps = denser store stream =
// higher sustained DRAM bandwidth. All cache-hint experiments (R4 .cs store,
// R7 evict_last load) regressed and are permanently reverted.
__global__ __launch_bounds__(192, 8) void bert_embed_kernel(
    const float* __restrict__ seq,   // [B, V, 3]
    const float* __restrict__ fw,    // [V, E]
    const float* __restrict__ fb,    // [V, E]
    const float* __restrict__ tw,    // [V, E]
    const float* __restrict__ tb,    // [V, E]
    float* __restrict__ out)         // [B, V, E]
{
    __shared__ float s_seq[BB * 3];  // 48 floats

    const int v = blockIdx.x;
    const int t = threadIdx.x;
    const int e = t * 4;                       // even-aligned
    const size_t base = (size_t)v * EE + e;

    // Stage seq for this v: thread t<48 loads (b = t/3, ch = t%3).
    if (t < BB * 3) {
        const int b = t / 3, ch = t % 3;
        s_seq[t] = __ldg(seq + ((size_t)b * VV + v) * 3 + ch);
    }

    // Compulsory weight reads, kept in registers across the batch loop.
    const float4 wf = *reinterpret_cast<const float4*>(fw + base);
    const float4 bf = *reinterpret_cast<const float4*>(fb + base);
    const float4 wt = *reinterpret_cast<const float4*>(tw + base);
    const float4 bt = *reinterpret_cast<const float4*>(tb + base);

    // Combined bias: out = s0*wf + s2*wt + (bf+bt) + pe  (saves 4 regs)
    const float4 bs = make_float4(bf.x + bt.x, bf.y + bt.y,
                                  bf.z + bt.z, bf.w + bt.w);

    // div_term[i] = exp(2i * (-ln(10000)/E)); here 2i = e and e+2.
    const float c  = -9.210340371976184f / (float)EE;   // -ln(10000)/E
    const float d0 = __expf((float)e * c);
    const float d1 = __expf((float)(e + 2) * c);

    __syncthreads();

    #pragma unroll
    for (int b = 0; b < BB; b++) {
        const float s0 = s_seq[b * 3 + 0];   // flux (LDS broadcast)
        const float s1 = s_seq[b * 3 + 1];   // passend
        const float s2 = s_seq[b * 3 + 2];   // time

        float sin0, cos0, sin1, cos1;
        __sincosf(s1 * d0, &sin0, &cos0);
        __sincosf(s1 * d1, &sin1, &cos1);

        float4 o;
        o.x = fmaf(s0, wf.x, fmaf(s2, wt.x, bs.x)) + sin0;
        o.y = fmaf(s0, wf.y, fmaf(s2, wt.y, bs.y)) + cos0;
        o.z = fmaf(s0, wf.z, fmaf(s2, wt.z, bs.z)) + sin1;
        o.w = fmaf(s0, wf.w, fmaf(s2, wt.w, bs.w)) + cos1;

        // Plain cached store (STG.128) — best-measured write path.
        *reinterpret_cast<float4*>(out + (size_t)b * (VV * EE) + base) = o;
    }
}

extern "C" void kernel_launch(void* const* d_in, const int* in_sizes, int n_in,
                              void* d_out, int out_size)
{
    const float* seq = (const float*)d_in[0];  // sequence [B,V,3]
    const float* fw  = (const float*)d_in[1];  // flux_w   [V,E]
    const float* fb  = (const float*)d_in[2];  // flux_b   [V,E]
    const float* tw  = (const float*)d_in[3];  // time_w   [V,E]
    const float* tb  = (const float*)d_in[4];  // time_b   [V,E]
    float* out = (float*)d_out;                // [B,V,E]

    dim3 grid(VV);
    dim3 block(EE / 4);  // 192 threads
    bert_embed_kernel<<<grid, block>>>(seq, fw, fb, tw, tb, out);
}

// round 10
// speedup vs baseline: 1.3589x; 1.0877x over previous
#include <cuda_runtime.h>
#include <cuda_bf16.h>

// Problem constants: B=16, V=4096, E=768
#define BB 16
#define VV 4096
#define EE 768

// out[b,v,e] = seq[b,v,0]*flux_w[v,e] + flux_b[v,e]
//            + seq[b,v,2]*time_w[v,e] + time_b[v,e]
//            + (e even ? sin : cos)( seq[b,v,1] * exp(-e_even*ln(10000)/E) )
//
// R9 = R5 structure with __launch_bounds__(192, 7): 48-reg cap -> 7 blocks
// (42 warps/SM, 65% theoretical occ) WITHOUT spilling. R8's (192,8)=40 regs
// spilled (L1 56->77%, DRAM 65->54); live state (~36 values) fits in 48.
// Cache-hint experiments (.cs store R4, evict_last load R7) are dead ends —
// both throttled L1tex. Plain LDG.128 / STG.128 is the proven path.
__global__ __launch_bounds__(192, 7) void bert_embed_kernel(
    const float* __restrict__ seq,   // [B, V, 3]
    const float* __restrict__ fw,    // [V, E]
    const float* __restrict__ fb,    // [V, E]
    const float* __restrict__ tw,    // [V, E]
    const float* __restrict__ tb,    // [V, E]
    float* __restrict__ out)         // [B, V, E]
{
    __shared__ float s_seq[BB * 3];  // 48 floats

    const int v = blockIdx.x;
    const int t = threadIdx.x;
    const int e = t * 4;                       // even-aligned
    const size_t base = (size_t)v * EE + e;

    // Stage seq for this v: thread t<48 loads (b = t/3, ch = t%3).
    if (t < BB * 3) {
        const int b = t / 3, ch = t % 3;
        s_seq[t] = __ldg(seq + ((size_t)b * VV + v) * 3 + ch);
    }

    // Compulsory weight reads, kept in registers across the batch loop.
    const float4 wf = *reinterpret_cast<const float4*>(fw + base);
    const float4 bf = *reinterpret_cast<const float4*>(fb + base);
    const float4 wt = *reinterpret_cast<const float4*>(tw + base);
    const float4 bt = *reinterpret_cast<const float4*>(tb + base);

    // Combined bias: out = s0*wf + s2*wt + (bf+bt) + pe  (saves 4 regs)
    const float4 bs = make_float4(bf.x + bt.x, bf.y + bt.y,
                                  bf.z + bt.z, bf.w + bt.w);

    // div_term[i] = exp(2i * (-ln(10000)/E)); here 2i = e and e+2.
    const float c  = -9.210340371976184f / (float)EE;   // -ln(10000)/E
    const float d0 = __expf((float)e * c);
    const float d1 = __expf((float)(e + 2) * c);

    __syncthreads();

    #pragma unroll
    for (int b = 0; b < BB; b++) {
        const float s0 = s_seq[b * 3 + 0];   // flux (LDS broadcast)
        const float s1 = s_seq[b * 3 + 1];   // passend
        const float s2 = s_seq[b * 3 + 2];   // time

        float sin0, cos0, sin1, cos1;
        __sincosf(s1 * d0, &sin0, &cos0);
        __sincosf(s1 * d1, &sin1, &cos1);

        float4 o;
        o.x = fmaf(s0, wf.x, fmaf(s2, wt.x, bs.x)) + sin0;
        o.y = fmaf(s0, wf.y, fmaf(s2, wt.y, bs.y)) + cos0;
        o.z = fmaf(s0, wf.z, fmaf(s2, wt.z, bs.z)) + sin1;
        o.w = fmaf(s0, wf.w, fmaf(s2, wt.w, bs.w)) + cos1;

        // Plain cached store (STG.128) — best-measured write path.
        *reinterpret_cast<float4*>(out + (size_t)b * (VV * EE) + base) = o;
    }
}

extern "C" void kernel_launch(void* const* d_in, const int* in_sizes, int n_in,
                              void* d_out, int out_size)
{
    const float* seq = (const float*)d_in[0];  // sequence [B,V,3]
    const float* fw  = (const float*)d_in[1];  // flux_w   [V,E]
    const float* fb  = (const float*)d_in[2];  // flux_b   [V,E]
    const float* tw  = (const float*)d_in[3];  // time_w   [V,E]
    const float* tb  = (const float*)d_in[4];  // time_b   [V,E]
    float* out = (float*)d_out;                // [B,V,E]

    dim3 grid(VV);
    dim3 block(EE / 4);  // 192 threads
    bert_embed_kernel<<<grid, block>>>(seq, fw, fb, tw, tb, out);
}

// round 11
// speedup vs baseline: 1.3760x; 1.0126x over previous
#include <cuda_runtime.h>
#include <cuda_bf16.h>
#include <cstdint>

// Problem constants: B=16, V=4096, E=768
#define BB 16
#define VV 4096
#define EE 768

// out[b,v,e] = seq[b,v,0]*flux_w[v,e] + flux_b[v,e]
//            + seq[b,v,2]*time_w[v,e] + time_b[v,e]
//            + (e even ? sin : cos)( seq[b,v,1] * exp(-e_even*ln(10000)/E) )
//
// R10: write-path restructure. Evidence so far: DRAM traffic is already
// compulsory (~196 MB = writes only), every pipe <30%, and three different
// configs all cap at 5.1-5.2 TB/s (65%) -> the binder is HBM WRITE
// EFFICIENCY (row-buffer thrash from ~6K interleaved 512B store streams).
// Fix: assemble each 3KB output row in SMEM, emit it as ONE cp.async.bulk
// shared->global store (TMA path, contiguous 3KB burst, L1 bypass).
// Double-buffered; wait_group<1> backpressure; weights still register-
// resident across the b-loop (traffic unchanged, only burst shape changes).

__device__ __forceinline__ uint32_t smem_u32(const void* p) {
    return (uint32_t)__cvta_generic_to_shared(p);
}

__global__ __launch_bounds__(192) void bert_embed_kernel(
    const float* __restrict__ seq,   // [B, V, 3]
    const float* __restrict__ fw,    // [V, E]
    const float* __restrict__ fb,    // [V, E]
    const float* __restrict__ tw,    // [V, E]
    const float* __restrict__ tb,    // [V, E]
    float* __restrict__ out)         // [B, V, E]
{
    __shared__ __align__(16) float buf[2][EE];  // 2 x 3KB row buffers
    __shared__ float s_seq[BB * 3];             // 48 floats

    const int v = blockIdx.x;
    const int t = threadIdx.x;
    const int e = t * 4;                        // even-aligned
    const size_t base = (size_t)v * EE + e;

    // Stage seq for this v: thread t<48 loads (b = t/3, ch = t%3).
    if (t < BB * 3) {
        const int b = t / 3, ch = t % 3;
        s_seq[t] = __ldg(seq + ((size_t)b * VV + v) * 3 + ch);
    }

    // Compulsory weight reads, register-resident across the batch loop.
    const float4 wf = *reinterpret_cast<const float4*>(fw + base);
    const float4 bf = *reinterpret_cast<const float4*>(fb + base);
    const float4 wt = *reinterpret_cast<const float4*>(tw + base);
    const float4 bt = *reinterpret_cast<const float4*>(tb + base);
    const float4 bs = make_float4(bf.x + bt.x, bf.y + bt.y,
                                  bf.z + bt.z, bf.w + bt.w);

    // div_term[i] = exp(2i * (-ln(10000)/E)); here 2i = e and e+2.
    const float c  = -9.210340371976184f / (float)EE;   // -ln(10000)/E
    const float d0 = __expf((float)e * c);
    const float d1 = __expf((float)(e + 2) * c);

    __syncthreads();

    #pragma unroll
    for (int b = 0; b < BB; b++) {
        // Buffer reuse gate: the bulk store issued at iter b-2 (same buffer)
        // must have drained. wait_group 1 leaves only iter b-1 in flight.
        if (b >= 2) {
            if (t == 0) asm volatile("cp.async.bulk.wait_group 1;" ::: "memory");
            __syncthreads();
        }

        const float s0 = s_seq[b * 3 + 0];   // flux (LDS broadcast)
        const float s1 = s_seq[b * 3 + 1];   // passend
        const float s2 = s_seq[b * 3 + 2];   // time

        float sin0, cos0, sin1, cos1;
        __sincosf(s1 * d0, &sin0, &cos0);
        __sincosf(s1 * d1, &sin1, &cos1);

        float4 o;
        o.x = fmaf(s0, wf.x, fmaf(s2, wt.x, bs.x)) + sin0;
        o.y = fmaf(s0, wf.y, fmaf(s2, wt.y, bs.y)) + cos0;
        o.z = fmaf(s0, wf.z, fmaf(s2, wt.z, bs.z)) + sin1;
        o.w = fmaf(s0, wf.w, fmaf(s2, wt.w, bs.w)) + cos1;

        // Stage the row in SMEM (STS.128), then one 3KB bulk store.
        *reinterpret_cast<float4*>(&buf[b & 1][e]) = o;
        __syncthreads();

        if (t == 0) {
            // Make generic STS visible to the async proxy, then DMA the row.
            asm volatile("fence.proxy.async.shared::cta;" ::: "memory");
            const float* gdst = out + (size_t)b * (VV * EE) + (size_t)v * EE;
            asm volatile(
                "cp.async.bulk.global.shared::cta.bulk_group [%0], [%1], %2;"
                :: "l"(gdst), "r"(smem_u32(&buf[b & 1][0])), "r"(EE * 4)
                : "memory");
            asm volatile("cp.async.bulk.commit_group;" ::: "memory");
        }
    }

    // Drain all outstanding bulk stores before exit.
    if (t == 0) asm volatile("cp.async.bulk.wait_group 0;" ::: "memory");
}

extern "C" void kernel_launch(void* const* d_in, const int* in_sizes, int n_in,
                              void* d_out, int out_size)
{
    const float* seq = (const float*)d_in[0];  // sequence [B,V,3]
    const float* fw  = (const float*)d_in[1];  // flux_w   [V,E]
    const float* fb  = (const float*)d_in[2];  // flux_b   [V,E]
    const float* tw  = (const float*)d_in[3];  // time_w   [V,E]
    const float* tb  = (const float*)d_in[4];  // time_b   [V,E]
    float* out = (float*)d_out;                // [B,V,E]

    dim3 grid(VV);
    dim3 block(EE / 4);  // 192 threads
    bert_embed_kernel<<<grid, block>>>(seq, fw, fb, tw, tb, out);
}